// round 4
// baseline (speedup 1.0000x reference)
#include <cuda_runtime.h>

// Problem constants
#define B_ 8
#define C_ 256
#define N_ 16384
#define K_ 128

// Tiling
#define TN 128                  // points per chunk
#define TC 64                   // channels per tile block
#define SPLITS 19               // 8*19 = 152 CTAs = #SMs
#define TPB 1024
#define TAB_ELEMS (K_ * C_)     // 32768 per-CTA table entries
#define NCHUNK (N_ / TN)        // 128
#define TSTRIDE 68              // tile row stride in floats (16B-aligned rows, qw-conflict-free)

// Per-CTA partial tables (ordered-uint keys). ~19.9 MB.
__device__ unsigned int g_scratch[B_ * SPLITS * TAB_ELEMS];

// Monotone float -> uint key: unsigned order == float order.
__device__ __forceinline__ unsigned int fkey(float f) {
    int i = __float_as_int(f);
    return (i >= 0) ? ((unsigned int)i | 0x80000000u) : ~(unsigned int)i;
}
__device__ __forceinline__ float funkey(unsigned int k) {
    unsigned int i = (k & 0x80000000u) ? (k & 0x7FFFFFFFu) : ~k;
    return __int_as_float((int)i);
}

// Phase 1: fused transpose + per-CTA segment-max, register-pipelined, all-vector smem.
__global__ __launch_bounds__(TPB, 1)
void seg_phase1(const float* __restrict__ pf, const int* __restrict__ cids,
                float* __restrict__ out_pf) {
    extern __shared__ unsigned int smem[];
    unsigned int* tab = smem;                          // K*C keys, 128 KB
    float* tile = (float*)(smem + TAB_ELEMS);          // [TN][TSTRIDE] point-major
    int* scid = (int*)(tile + TN * TSTRIDE);           // TN ids

    const int tid = threadIdx.x;
    const int b = blockIdx.y;
    const int s = blockIdx.x;

    // init table (vectorized)
    {
        uint4 z = make_uint4(0u, 0u, 0u, 0u);
        uint4* t4 = (uint4*)tab;
        #pragma unroll
        for (int i = tid; i < TAB_ELEMS / 4; i += TPB) t4[i] = z;
    }

    const float* src = pf + (size_t)b * C_ * N_;

    // Loader mapping: thread owns point ln, channel groups cg4 and cg4+32
    const int ln = tid & 127;
    const int cg4 = (tid >> 7) * 4;     // 0,4,...,28
    // Consumer mapping: 4 consecutive channels per thread; warp = 2 points
    const int c4 = (tid & 15) * 4;      // 0..60
    const int pb = tid >> 4;            // 0..63

    int m = s, cb = 0;
    int cidreg = 0;
    if (tid < TN) cidreg = cids[b * N_ + m * TN + tid];

    float r[8];
    {   // prime: block (m=s, cb=0)
        const float* p0 = src + (size_t)cg4 * N_ + m * TN + ln;
        #pragma unroll
        for (int j = 0; j < 4; j++) {
            r[j]     = __ldcs(p0 + (size_t)j * N_);
            r[4 + j] = __ldcs(p0 + (size_t)(32 + j) * N_);
        }
    }

    bool have = true;
    while (have) {
        __syncthreads();                               // prev tile fully consumed
        // STS.128 x2, quarter-warp conflict-free
        *(float4*)(tile + ln * TSTRIDE + cg4)      = make_float4(r[0], r[1], r[2], r[3]);
        *(float4*)(tile + ln * TSTRIDE + cg4 + 32) = make_float4(r[4], r[5], r[6], r[7]);
        if (cb == 0 && tid < TN) scid[tid] = cidreg;
        __syncthreads();                               // tile + scid ready

        const int n0 = m * TN;
        const int curcb = cb;

        // advance + prefetch next block (hides LDG latency under consume)
        int nm = m, ncb = cb + TC;
        if (ncb == C_) { ncb = 0; nm = m + SPLITS; }
        have = (nm < NCHUNK);
        if (have) {
            const float* p0 = src + (size_t)(ncb + cg4) * N_ + nm * TN + ln;
            #pragma unroll
            for (int j = 0; j < 4; j++) {
                r[j]     = __ldcs(p0 + (size_t)j * N_);
                r[4 + j] = __ldcs(p0 + (size_t)(32 + j) * N_);
            }
            if (ncb == 0 && tid < TN) cidreg = cids[b * N_ + nm * TN + tid];
        }

        // consume: LDS.128 tile -> STG.128 transpose + vector-filtered shared atomicMax
        #pragma unroll
        for (int q = 0; q < 2; q++) {
            const int p = pb + q * 64;
            float4 vv = *(const float4*)(tile + p * TSTRIDE + c4);
            __stcs((float4*)(out_pf + ((size_t)b * N_ + n0 + p) * C_ + curcb + c4), vv);
            const int cid = scid[p];
            if (cid >= 0) {
                unsigned int* cell = &tab[cid * C_ + curcb + c4];
                uint4 cur = *(const uint4*)cell;       // LDS.128 filter read
                unsigned int k0 = fkey(vv.x); if (cur.x < k0) atomicMax(cell + 0, k0);
                unsigned int k1 = fkey(vv.y); if (cur.y < k1) atomicMax(cell + 1, k1);
                unsigned int k2 = fkey(vv.z); if (cur.z < k2) atomicMax(cell + 2, k2);
                unsigned int k3 = fkey(vv.w); if (cur.w < k3) atomicMax(cell + 3, k3);
            }
        }
        m = nm; cb = ncb;
    }
    __syncthreads();

    // dump private table to scratch (vectorized, streaming)
    uint4* dst = (uint4*)(g_scratch + ((size_t)b * SPLITS + s) * TAB_ELEMS);
    const uint4* t4 = (const uint4*)tab;
    #pragma unroll
    for (int i = tid; i < TAB_ELEMS / 4; i += TPB)
        __stcs(dst + i, t4[i]);
}

// Phase 2: 2 threads per uint4 output (10/9 split of 19 partials), shfl combine.
__global__ void seg_phase2(float* __restrict__ out_seg) {
    const int J4 = TAB_ELEMS / 4;                       // 8192 uint4 per batch
    int g = blockIdx.x * blockDim.x + threadIdx.x;      // 0 .. 2*B*J4-1
    int j = g >> 1;                                     // output uint4 index
    int half = g & 1;
    int b = j / J4;
    int j4 = j - b * J4;
    const uint4* p = (const uint4*)g_scratch + (size_t)b * SPLITS * J4 + j4;
    int s0 = half * 10;
    int s1 = s0 + (half ? 9 : 10);
    uint4 mx = make_uint4(0u, 0u, 0u, 0u);
    #pragma unroll
    for (int s = s0; s < s1; s++) {
        uint4 v = __ldcs(p + (size_t)s * J4);
        mx.x = max(mx.x, v.x); mx.y = max(mx.y, v.y);
        mx.z = max(mx.z, v.z); mx.w = max(mx.w, v.w);
    }
    mx.x = max(mx.x, __shfl_xor_sync(0xFFFFFFFFu, mx.x, 1));
    mx.y = max(mx.y, __shfl_xor_sync(0xFFFFFFFFu, mx.y, 1));
    mx.z = max(mx.z, __shfl_xor_sync(0xFFFFFFFFu, mx.z, 1));
    mx.w = max(mx.w, __shfl_xor_sync(0xFFFFFFFFu, mx.w, 1));
    if (half == 0) {
        float4 o;
        o.x = mx.x ? funkey(mx.x) : 0.0f;
        o.y = mx.y ? funkey(mx.y) : 0.0f;
        o.z = mx.z ? funkey(mx.z) : 0.0f;
        o.w = mx.w ? funkey(mx.w) : 0.0f;
        ((float4*)out_seg)[j] = o;
    }
}

extern "C" void kernel_launch(void* const* d_in, const int* in_sizes, int n_in,
                              void* d_out, int out_size) {
    const float* pf = (const float*)d_in[0];      // (B,C,N) f32
    const int* cid  = (const int*)d_in[1];        // (B,N) i32
    float* out      = (float*)d_out;
    float* out_seg  = out;                        // (B*K, C)
    float* out_pf   = out + (size_t)B_ * K_ * C_; // (B*N, C)

    const size_t smem_bytes = (size_t)TAB_ELEMS * 4 + (size_t)TN * TSTRIDE * 4 + (size_t)TN * 4;
    cudaFuncSetAttribute(seg_phase1, cudaFuncAttributeMaxDynamicSharedMemorySize,
                         (int)smem_bytes);

    dim3 grid(SPLITS, B_);
    seg_phase1<<<grid, TPB, smem_bytes>>>(pf, cid, out_pf);

    const int threads2 = 2 * B_ * (TAB_ELEMS / 4);   // 131072
    seg_phase2<<<threads2 / 256, 256>>>(out_seg);
}

// round 5
// speedup vs baseline: 1.0862x; 1.0862x over previous
#include <cuda_runtime.h>

// Problem constants
#define B_ 8
#define C_ 256
#define N_ 16384
#define K_ 128

// Tiling
#define TN 128                  // points per chunk
#define TC 64                   // channels per tile block
#define SPLITS 19               // 8*19 = 152 CTAs = #SMs
#define TPB 1024
#define TAB_ELEMS (K_ * C_)     // 32768 per-CTA table entries
#define NCHUNK (N_ / TN)        // 128
#define TSTRIDE 68              // tile row stride in floats

// Per-CTA partial tables (ordered-uint keys). ~19.9 MB — intentionally L2-resident.
__device__ unsigned int g_scratch[B_ * SPLITS * TAB_ELEMS];

// Monotone float -> uint key: unsigned order == float order.
__device__ __forceinline__ unsigned int fkey(float f) {
    int i = __float_as_int(f);
    return (i >= 0) ? ((unsigned int)i | 0x80000000u) : ~(unsigned int)i;
}
__device__ __forceinline__ float funkey(unsigned int k) {
    unsigned int i = (k & 0x80000000u) ? (k & 0x7FFFFFFFu) : ~k;
    return __int_as_float((int)i);
}

// Phase 1: fused transpose + per-CTA segment-max, 2-deep register pipeline.
__global__ __launch_bounds__(TPB, 1)
void seg_phase1(const float* __restrict__ pf, const int* __restrict__ cids,
                float* __restrict__ out_pf) {
    extern __shared__ unsigned int smem[];
    unsigned int* tab = smem;                          // K*C keys, 128 KB
    float* tile = (float*)(smem + TAB_ELEMS);          // [TN][TSTRIDE] point-major
    int* scid = (int*)(tile + TN * TSTRIDE);           // TN ids

    const int tid = threadIdx.x;
    const int b = blockIdx.y;
    const int s = blockIdx.x;

    {   // init table (vectorized)
        uint4 z = make_uint4(0u, 0u, 0u, 0u);
        uint4* t4 = (uint4*)tab;
        #pragma unroll
        for (int i = tid; i < TAB_ELEMS / 4; i += TPB) t4[i] = z;
    }

    const float* src = pf + (size_t)b * C_ * N_;

    // Loader mapping: thread owns point ln, channel quads cg4 and cg4+32
    const int ln = tid & 127;
    const int cg4 = (tid >> 7) * 4;     // 0,4,...,28
    // Consumer mapping: 4 consecutive channels per thread; warp = 2 points
    const int c4 = (tid & 15) * 4;      // 0..60
    const int pb = tid >> 4;            // 0..63

    auto prefetch = [&](int mm, int cbb, float* rr, int& cidr) {
        const float* p0 = src + (size_t)(cbb + cg4) * N_ + mm * TN + ln;
        #pragma unroll
        for (int j = 0; j < 4; j++) {
            rr[j]     = __ldcs(p0 + (size_t)j * N_);
            rr[4 + j] = __ldcs(p0 + (size_t)(32 + j) * N_);
        }
        if (cbb == 0 && tid < TN) cidr = cids[b * N_ + mm * TN + tid];
    };

    // pipeline state: current block (mC,cbC), next block (mN,cbN)
    int mC = s, cbC = 0;
    int mN = s, cbN = TC;
    bool haveN;
    { int t = cbN; if (t == C_) { cbN = 0; mN += SPLITS; } haveN = (mN < NCHUNK); }

    float rA[8], rB[8];
    int cidA = 0, cidB = 0;
    prefetch(mC, cbC, rA, cidA);
    if (haveN) prefetch(mN, cbN, rB, cidB);

    // one pipeline step: consume current (held in rr), prefetch block current+2 into rr
    auto step = [&](float* rr, int& cidr) -> bool {
        __syncthreads();                               // prev tile fully consumed
        *(float4*)(tile + ln * TSTRIDE + cg4)      = make_float4(rr[0], rr[1], rr[2], rr[3]);
        *(float4*)(tile + ln * TSTRIDE + cg4 + 32) = make_float4(rr[4], rr[5], rr[6], rr[7]);
        if (cbC == 0 && tid < TN) scid[tid] = cidr;
        __syncthreads();                               // tile + scid ready

        // coords of block current+2; prefetch into the now-free buffer rr
        int m2 = mN, cb2 = cbN;
        bool have2 = haveN;
        if (have2) {
            cb2 += TC;
            if (cb2 == C_) { cb2 = 0; m2 += SPLITS; }
            have2 = (m2 < NCHUNK);
        }
        if (have2) prefetch(m2, cb2, rr, cidr);

        // consume current block from smem
        const int n0 = mC * TN;
        const int curcb = cbC;
        #pragma unroll
        for (int q = 0; q < 2; q++) {
            const int p = pb + q * 64;
            float4 vv = *(const float4*)(tile + p * TSTRIDE + c4);
            __stcs((float4*)(out_pf + ((size_t)b * N_ + n0 + p) * C_ + curcb + c4), vv);
            const int cid = scid[p];
            if (cid >= 0) {
                unsigned int* cell = &tab[cid * C_ + curcb + c4];
                uint4 cur = *(const uint4*)cell;
                unsigned int k0 = fkey(vv.x); if (cur.x < k0) atomicMax(cell + 0, k0);
                unsigned int k1 = fkey(vv.y); if (cur.y < k1) atomicMax(cell + 1, k1);
                unsigned int k2 = fkey(vv.z); if (cur.z < k2) atomicMax(cell + 2, k2);
                unsigned int k3 = fkey(vv.w); if (cur.w < k3) atomicMax(cell + 3, k3);
            }
        }

        // rotate pipeline state
        bool cont = haveN;
        mC = mN; cbC = cbN;
        mN = m2; cbN = cb2;
        haveN = have2;
        return cont;
    };

    // total block count per CTA is a multiple of 4 (C_/TC = 4 c-blocks/chunk),
    // so alternating A/B steps terminates cleanly at the while check.
    bool run = true;
    while (run) {
        run = step(rA, cidA);
        if (!run) break;
        run = step(rB, cidB);
    }
    __syncthreads();

    // dump private table to scratch — PLAIN stores so it stays in L2 for phase2
    uint4* dst = (uint4*)(g_scratch + ((size_t)b * SPLITS + s) * TAB_ELEMS);
    const uint4* t4 = (const uint4*)tab;
    #pragma unroll
    for (int i = tid; i < TAB_ELEMS / 4; i += TPB) dst[i] = t4[i];
}

// Phase 2: 2 threads per uint4 output (10/9 split of 19 partials), shfl combine.
// Plain loads — scratch is L2-resident.
__global__ void seg_phase2(float* __restrict__ out_seg) {
    const int J4 = TAB_ELEMS / 4;                       // 8192 uint4 per batch
    int g = blockIdx.x * blockDim.x + threadIdx.x;      // 0 .. 2*B*J4-1
    int j = g >> 1;                                     // output uint4 index
    int half = g & 1;
    int b = j / J4;
    int j4 = j - b * J4;
    const uint4* p = (const uint4*)g_scratch + (size_t)b * SPLITS * J4 + j4;
    int s0 = half * 10;
    int s1 = s0 + (half ? 9 : 10);
    uint4 mx = make_uint4(0u, 0u, 0u, 0u);
    #pragma unroll
    for (int s = s0; s < s1; s++) {
        uint4 v = p[(size_t)s * J4];
        mx.x = max(mx.x, v.x); mx.y = max(mx.y, v.y);
        mx.z = max(mx.z, v.z); mx.w = max(mx.w, v.w);
    }
    mx.x = max(mx.x, __shfl_xor_sync(0xFFFFFFFFu, mx.x, 1));
    mx.y = max(mx.y, __shfl_xor_sync(0xFFFFFFFFu, mx.y, 1));
    mx.z = max(mx.z, __shfl_xor_sync(0xFFFFFFFFu, mx.z, 1));
    mx.w = max(mx.w, __shfl_xor_sync(0xFFFFFFFFu, mx.w, 1));
    if (half == 0) {
        float4 o;
        o.x = mx.x ? funkey(mx.x) : 0.0f;
        o.y = mx.y ? funkey(mx.y) : 0.0f;
        o.z = mx.z ? funkey(mx.z) : 0.0f;
        o.w = mx.w ? funkey(mx.w) : 0.0f;
        ((float4*)out_seg)[j] = o;
    }
}

extern "C" void kernel_launch(void* const* d_in, const int* in_sizes, int n_in,
                              void* d_out, int out_size) {
    const float* pf = (const float*)d_in[0];      // (B,C,N) f32
    const int* cid  = (const int*)d_in[1];        // (B,N) i32
    float* out      = (float*)d_out;
    float* out_seg  = out;                        // (B*K, C)
    float* out_pf   = out + (size_t)B_ * K_ * C_; // (B*N, C)

    const size_t smem_bytes = (size_t)TAB_ELEMS * 4 + (size_t)TN * TSTRIDE * 4 + (size_t)TN * 4;
    cudaFuncSetAttribute(seg_phase1, cudaFuncAttributeMaxDynamicSharedMemorySize,
                         (int)smem_bytes);

    dim3 grid(SPLITS, B_);
    seg_phase1<<<grid, TPB, smem_bytes>>>(pf, cid, out_pf);

    const int threads2 = 2 * B_ * (TAB_ELEMS / 4);   // 131072
    seg_phase2<<<threads2 / 256, 256>>>(out_seg);
}

// round 6
// speedup vs baseline: 1.1513x; 1.0599x over previous
#include <cuda_runtime.h>

// Problem constants
#define B_ 8
#define C_ 256
#define N_ 16384
#define K_ 128

// Decomposition: CTA = (batch, 64-channel slice, quarter of N)
#define SLICE_C 64              // channels per CTA
#define NSLICE 4                // C_/SLICE_C
#define NS 4                    // N-splits
#define TN 128                  // points per chunk
#define TPB 1024
#define NITER (N_ / TN / NS)    // 32 chunks per CTA
#define TROW 68                 // padded row stride (floats/uints) for tile & table
#define TAB_U (K_ * TROW)       // 8704 uints per-CTA table (padded)

// Per-CTA partial tables: 128 CTAs x 8704 uints = ~4.5 MB (L2-resident).
__device__ unsigned int g_scratch[B_ * NSLICE * NS * TAB_U];

// Monotone float -> uint key: unsigned order == float order.
__device__ __forceinline__ unsigned int fkey(float f) {
    int i = __float_as_int(f);
    return (i >= 0) ? ((unsigned int)i | 0x80000000u) : ~(unsigned int)i;
}
__device__ __forceinline__ float funkey(unsigned int k) {
    unsigned int i = (k & 0x80000000u) ? (k & 0x7FFFFFFFu) : ~k;
    return __int_as_float((int)i);
}

// Phase 1: fused transpose + per-CTA (64ch-slice) segment-max, 2-deep reg pipeline.
__global__ __launch_bounds__(TPB, 1)
void seg_phase1(const float* __restrict__ pf, const int* __restrict__ cids,
                float* __restrict__ out_pf) {
    extern __shared__ unsigned int smem[];
    unsigned int* tab = smem;                          // [K][TROW] keys, 34.8 KB
    float* tile = (float*)(smem + TAB_U);              // [TN][TROW] point-major
    int* scid = (int*)(tile + TN * TROW);              // TN ids

    const int tid = threadIdx.x;
    const int b = blockIdx.y;
    const int cslice = blockIdx.x >> 2;                // 0..3
    const int ns = blockIdx.x & 3;                     // 0..3

    {   // init table (vectorized; includes pad columns — harmless)
        uint4 z = make_uint4(0u, 0u, 0u, 0u);
        uint4* t4 = (uint4*)tab;
        #pragma unroll
        for (int i = tid; i < TAB_U / 4; i += TPB) t4[i] = z;
    }

    const float* src = pf + (size_t)b * C_ * N_ + (size_t)cslice * SLICE_C * N_;
    const int* cidp = cids + b * N_;

    // Loader mapping: thread owns point ln, channel quads cg4 and cg4+32 (in-slice)
    const int ln = tid & 127;
    const int cg4 = (tid >> 7) * 4;     // 0,4,...,28
    // Consumer mapping: 4 consecutive in-slice channels per thread; warp = 2 points
    const int c4 = (tid & 15) * 4;      // 0..60
    const int pb = tid >> 4;            // 0..63

    auto mOf = [&](int i) { return ns + NS * i; };

    auto prefetch = [&](int i, float* rr, int& cidr) {
        const int m = mOf(i);
        const float* p0 = src + (size_t)cg4 * N_ + m * TN + ln;
        #pragma unroll
        for (int j = 0; j < 4; j++) {
            rr[j]     = __ldcs(p0 + (size_t)j * N_);
            rr[4 + j] = __ldcs(p0 + (size_t)(32 + j) * N_);
        }
        if (tid < TN) cidr = cidp[m * TN + tid];
    };

    float rA[8], rB[8];
    int cidA = 0, cidB = 0;
    prefetch(0, rA, cidA);
    prefetch(1, rB, cidB);

    auto body = [&](int i, float* rr, int& cidr) {
        __syncthreads();                               // prev tile fully consumed
        *(float4*)(tile + ln * TROW + cg4)      = make_float4(rr[0], rr[1], rr[2], rr[3]);
        *(float4*)(tile + ln * TROW + cg4 + 32) = make_float4(rr[4], rr[5], rr[6], rr[7]);
        if (tid < TN) scid[tid] = cidr;
        __syncthreads();                               // tile + scid ready

        if (i + 2 < NITER) prefetch(i + 2, rr, cidr);  // refill freed buffer

        const int n0 = mOf(i) * TN;
        #pragma unroll
        for (int q = 0; q < 2; q++) {
            const int p = pb + q * 64;
            float4 vv = *(const float4*)(tile + p * TROW + c4);
            __stcs((float4*)(out_pf + ((size_t)b * N_ + n0 + p) * C_
                             + cslice * SLICE_C + c4), vv);
            const int cid = scid[p];
            if (cid >= 0) {
                unsigned int* cell = &tab[cid * TROW + c4];
                uint4 cur = *(const uint4*)cell;       // LDS.128 filter read
                unsigned int k0 = fkey(vv.x); if (cur.x < k0) atomicMax(cell + 0, k0);
                unsigned int k1 = fkey(vv.y); if (cur.y < k1) atomicMax(cell + 1, k1);
                unsigned int k2 = fkey(vv.z); if (cur.z < k2) atomicMax(cell + 2, k2);
                unsigned int k3 = fkey(vv.w); if (cur.w < k3) atomicMax(cell + 3, k3);
            }
        }
    };

    #pragma unroll 1
    for (int i = 0; i < NITER; i += 2) {
        body(i,     rA, cidA);
        body(i + 1, rB, cidB);
    }
    __syncthreads();

    // dump padded table to scratch (plain stores -> L2-resident for phase2)
    uint4* dst = (uint4*)(g_scratch
                 + ((size_t)((b * NSLICE + cslice) * NS + ns)) * TAB_U);
    const uint4* t4 = (const uint4*)tab;
    #pragma unroll
    for (int i = tid; i < TAB_U / 4; i += TPB) dst[i] = t4[i];
}

// Phase 2: reduce NS=4 partials per output float4. 4.5 MB reads, mostly L2 hits.
__global__ void seg_phase2(float* __restrict__ out_seg) {
    int g = blockIdx.x * blockDim.x + threadIdx.x;     // 0 .. B*K*C/4-1 (65536)
    const int PER_B = K_ * C_ / 4;                     // 8192
    int b = g / PER_B;
    int rem = g - b * PER_B;
    int k = rem >> 6;                                  // 0..127
    int cg = rem & 63;                                 // float4 group within row
    int c = cg * 4;
    int slice = c >> 6;
    int cc = c & 63;                                   // in-slice channel
    const unsigned int* base = g_scratch
        + ((size_t)(b * NSLICE + slice) * NS) * TAB_U + k * TROW + cc;
    uint4 mx = make_uint4(0u, 0u, 0u, 0u);
    #pragma unroll
    for (int s = 0; s < NS; s++) {
        uint4 v = *(const uint4*)(base + (size_t)s * TAB_U);
        mx.x = max(mx.x, v.x); mx.y = max(mx.y, v.y);
        mx.z = max(mx.z, v.z); mx.w = max(mx.w, v.w);
    }
    float4 o;
    o.x = mx.x ? funkey(mx.x) : 0.0f;
    o.y = mx.y ? funkey(mx.y) : 0.0f;
    o.z = mx.z ? funkey(mx.z) : 0.0f;
    o.w = mx.w ? funkey(mx.w) : 0.0f;
    ((float4*)out_seg)[g] = o;
}

extern "C" void kernel_launch(void* const* d_in, const int* in_sizes, int n_in,
                              void* d_out, int out_size) {
    const float* pf = (const float*)d_in[0];      // (B,C,N) f32
    const int* cid  = (const int*)d_in[1];        // (B,N) i32
    float* out      = (float*)d_out;
    float* out_seg  = out;                        // (B*K, C)
    float* out_pf   = out + (size_t)B_ * K_ * C_; // (B*N, C)

    const size_t smem_bytes = (size_t)TAB_U * 4 + (size_t)TN * TROW * 4 + (size_t)TN * 4;
    cudaFuncSetAttribute(seg_phase1, cudaFuncAttributeMaxDynamicSharedMemorySize,
                         (int)smem_bytes);

    dim3 grid(NSLICE * NS, B_);                   // 16 x 8 = 128 CTAs
    seg_phase1<<<grid, TPB, smem_bytes>>>(pf, cid, out_pf);

    const int t2 = B_ * K_ * C_ / 4;              // 65536
    seg_phase2<<<t2 / 256, 256>>>(out_seg);
}

// round 7
// speedup vs baseline: 1.2753x; 1.1078x over previous
#include <cuda_runtime.h>

// Problem constants
#define B_ 8
#define C_ 256
#define N_ 16384
#define K_ 128

// Decomposition: CTA = (batch, 64-channel slice, 1-of-9 N interleave)
#define SLICE_C 64
#define NSLICE 4                // C_/SLICE_C
#define NS 9                    // N interleave factor -> 8*4*9 = 288 CTAs, 2/SM
#define TN 64                   // points per chunk
#define TPB 512
#define NCHUNKS (N_ / TN)       // 256 chunks total, round-robin over NS
#define TROW 68                 // padded row stride (floats/uints)
#define TAB_U (K_ * TROW)       // 8704 uints per-CTA table

// Per-CTA partial tables: 288 x 34.8KB ~= 10 MB (L2-resident for phase2).
__device__ unsigned int g_scratch[B_ * NSLICE * NS * TAB_U];

// Monotone float -> uint key: unsigned order == float order.
__device__ __forceinline__ unsigned int fkey(float f) {
    int i = __float_as_int(f);
    return (i >= 0) ? ((unsigned int)i | 0x80000000u) : ~(unsigned int)i;
}
__device__ __forceinline__ float funkey(unsigned int k) {
    unsigned int i = (k & 0x80000000u) ? (k & 0x7FFFFFFFu) : ~k;
    return __int_as_float((int)i);
}

// Phase 1: fused transpose + per-CTA segment-max, 2-deep reg pipeline, 2 CTAs/SM.
__global__ __launch_bounds__(TPB, 2)
void seg_phase1(const float* __restrict__ pf, const int* __restrict__ cids,
                float* __restrict__ out_pf) {
    extern __shared__ unsigned int smem[];
    unsigned int* tab = smem;                          // [K][TROW], 34.8 KB
    float* tile = (float*)(smem + TAB_U);              // [TN][TROW] point-major
    int* scid = (int*)(tile + TN * TROW);              // TN ids

    const int tid = threadIdx.x;
    const int b = blockIdx.y;
    const int cslice = blockIdx.x / NS;                // 0..3
    const int ns = blockIdx.x - cslice * NS;           // 0..8

    {   // init table
        uint4 z = make_uint4(0u, 0u, 0u, 0u);
        uint4* t4 = (uint4*)tab;
        #pragma unroll
        for (int i = tid; i < TAB_U / 4; i += TPB) t4[i] = z;
    }

    const float* src = pf + (size_t)b * C_ * N_ + (size_t)cslice * SLICE_C * N_;
    const int* cidp = cids + b * N_;

    // chunk count for this ns: 256 = 9*28 + 4 -> ns<4 get 29, else 28
    const int cnt = (NCHUNKS / NS) + (ns < (NCHUNKS % NS) ? 1 : 0);

    // Loader: thread owns point ln, channel quads cg4 and cg4+32 (in-slice)
    const int ln = tid & 63;
    const int cg4 = (tid >> 6) * 4;     // 0,4,...,28
    // Consumer: 4 consecutive channels per thread; warp = 2 points
    const int c4 = (tid & 15) * 4;      // 0..60
    const int pb = tid >> 4;            // 0..31

    auto prefetch = [&](int i, float* rr, int& cidr) {
        const int m = ns + NS * i;
        const float* p0 = src + (size_t)cg4 * N_ + m * TN + ln;
        #pragma unroll
        for (int j = 0; j < 4; j++) {
            rr[j]     = __ldcs(p0 + (size_t)j * N_);
            rr[4 + j] = __ldcs(p0 + (size_t)(32 + j) * N_);
        }
        if (tid < TN) cidr = cidp[m * TN + tid];
    };

    float rA[8], rB[8];
    int cidA = 0, cidB = 0;
    prefetch(0, rA, cidA);
    if (cnt > 1) prefetch(1, rB, cidB);

    auto body = [&](int i, float* rr, int& cidr) {
        __syncthreads();                               // prev tile fully consumed
        *(float4*)(tile + ln * TROW + cg4)      = make_float4(rr[0], rr[1], rr[2], rr[3]);
        *(float4*)(tile + ln * TROW + cg4 + 32) = make_float4(rr[4], rr[5], rr[6], rr[7]);
        if (tid < TN) scid[tid] = cidr;
        __syncthreads();                               // tile + scid ready

        if (i + 2 < cnt) prefetch(i + 2, rr, cidr);    // refill freed buffer

        const int n0 = (ns + NS * i) * TN;
        #pragma unroll
        for (int q = 0; q < 2; q++) {
            const int p = pb + q * 32;
            float4 vv = *(const float4*)(tile + p * TROW + c4);
            __stcs((float4*)(out_pf + ((size_t)b * N_ + n0 + p) * C_
                             + cslice * SLICE_C + c4), vv);
            const int cid = scid[p];
            if (cid >= 0) {
                unsigned int* cell = &tab[cid * TROW + c4];
                uint4 cur = *(const uint4*)cell;       // LDS.128 filter read
                unsigned int k0 = fkey(vv.x); if (cur.x < k0) atomicMax(cell + 0, k0);
                unsigned int k1 = fkey(vv.y); if (cur.y < k1) atomicMax(cell + 1, k1);
                unsigned int k2 = fkey(vv.z); if (cur.z < k2) atomicMax(cell + 2, k2);
                unsigned int k3 = fkey(vv.w); if (cur.w < k3) atomicMax(cell + 3, k3);
            }
        }
    };

    int i = 0;
    #pragma unroll 1
    for (; i + 1 < cnt; i += 2) {
        body(i,     rA, cidA);
        body(i + 1, rB, cidB);
    }
    if (i < cnt) body(i, rA, cidA);                    // odd tail
    __syncthreads();

    // dump table (plain stores -> L2-resident for phase2)
    uint4* dst = (uint4*)(g_scratch
                 + (size_t)((b * NSLICE + cslice) * NS + ns) * TAB_U);
    const uint4* t4 = (const uint4*)tab;
    #pragma unroll
    for (int i2 = tid; i2 < TAB_U / 4; i2 += TPB) dst[i2] = t4[i2];
}

// Phase 2: reduce NS=9 partials per output float4 (plain loads, L2 hits).
__global__ void seg_phase2(float* __restrict__ out_seg) {
    int g = blockIdx.x * blockDim.x + threadIdx.x;     // 0 .. B*K*C/4-1
    const int PER_B = K_ * C_ / 4;                     // 8192
    int b = g / PER_B;
    int rem = g - b * PER_B;
    int k = rem >> 6;
    int cg = rem & 63;
    int c = cg * 4;
    int slice = c >> 6;
    int cc = c & 63;
    const unsigned int* base = g_scratch
        + (size_t)((b * NSLICE + slice) * NS) * TAB_U + k * TROW + cc;
    uint4 mx = make_uint4(0u, 0u, 0u, 0u);
    #pragma unroll
    for (int s = 0; s < NS; s++) {
        uint4 v = *(const uint4*)(base + (size_t)s * TAB_U);
        mx.x = max(mx.x, v.x); mx.y = max(mx.y, v.y);
        mx.z = max(mx.z, v.z); mx.w = max(mx.w, v.w);
    }
    float4 o;
    o.x = mx.x ? funkey(mx.x) : 0.0f;
    o.y = mx.y ? funkey(mx.y) : 0.0f;
    o.z = mx.z ? funkey(mx.z) : 0.0f;
    o.w = mx.w ? funkey(mx.w) : 0.0f;
    ((float4*)out_seg)[g] = o;
}

extern "C" void kernel_launch(void* const* d_in, const int* in_sizes, int n_in,
                              void* d_out, int out_size) {
    const float* pf = (const float*)d_in[0];      // (B,C,N) f32
    const int* cid  = (const int*)d_in[1];        // (B,N) i32
    float* out      = (float*)d_out;
    float* out_seg  = out;                        // (B*K, C)
    float* out_pf   = out + (size_t)B_ * K_ * C_; // (B*N, C)

    const size_t smem_bytes = (size_t)TAB_U * 4 + (size_t)TN * TROW * 4 + (size_t)TN * 4;
    cudaFuncSetAttribute(seg_phase1, cudaFuncAttributeMaxDynamicSharedMemorySize,
                         (int)smem_bytes);

    dim3 grid(NSLICE * NS, B_);                   // 36 x 8 = 288 CTAs, 2/SM
    seg_phase1<<<grid, TPB, smem_bytes>>>(pf, cid, out_pf);

    const int t2 = B_ * K_ * C_ / 4;              // 65536
    seg_phase2<<<t2 / 256, 256>>>(out_seg);
}